// round 12
// baseline (speedup 1.0000x reference)
#include <cuda_runtime.h>
#include <cstdint>

// ---------------------------------------------------------------------------
// x: (32, 256, 64, 64) f32   v: (2, 64, 64)   W: (2, 256, 256)   T: (2, 64, 64)
// out = invWHT( sum_p soft( v_p * (W_p @ WHT(x)), T_p ) ) / 4096 + x
// ---------------------------------------------------------------------------

#define BATCH 32
#define CH    256
#define HW    4096
#define NIMG  (BATCH * CH)

__device__ float g_f2[(size_t)BATCH * CH * HW];   // WHT(x), tf32-rounded
__device__ float g_f6[(size_t)BATCH * CH * HW];   // pod-summed soft-thresholded
// W in tf32, pod-interleaved (m = 2*o + p, M=512), mma fragment order:
//   [kq8(32)][m16tile(32)][lane(32)][4 floats]
__device__ float g_WtF[32 * 32 * 32 * 4];

__device__ __forceinline__ float tf32_round(float v) {
    uint32_t u;
    asm("cvt.rna.tf32.f32 %0, %1;" : "=r"(u) : "f"(v));
    return __uint_as_float(u);
}

__device__ __forceinline__ float softthr(float s, float t) {
    float m = fmaxf(fabsf(s) - t, 0.0f);
    return copysignf(m, s);
}

// ---------------------------------------------------------------------------
// 64-pt WHT, 8 consecutive elements/thread; stages 1,2,4 register-local,
// stages 8,16,32 via shfl.xor masks 1,2,4.
// ---------------------------------------------------------------------------
__device__ __forceinline__ void wht8_local(float (&a)[8]) {
    #pragma unroll
    for (int j = 0; j < 8; j += 2) { float s = a[j] + a[j+1], d = a[j] - a[j+1]; a[j] = s; a[j+1] = d; }
    #pragma unroll
    for (int j0 = 0; j0 < 8; j0 += 4)
        #pragma unroll
        for (int j = j0; j < j0 + 2; j++) { float s = a[j] + a[j+2], d = a[j] - a[j+2]; a[j] = s; a[j+2] = d; }
    #pragma unroll
    for (int j = 0; j < 4; j++) { float s = a[j] + a[j+4], d = a[j] - a[j+4]; a[j] = s; a[j+4] = d; }
}

__device__ __forceinline__ void wht64_vec(float (&a)[8], float (&b)[8], int lane) {
    wht8_local(a);
    wht8_local(b);
    #pragma unroll
    for (int mask = 1; mask <= 4; mask <<= 1) {
        bool hi = (lane & mask) != 0;
        #pragma unroll
        for (int i = 0; i < 8; i++) {
            float pa = __shfl_xor_sync(0xffffffffu, a[i], mask);
            float pb = __shfl_xor_sync(0xffffffffu, b[i], mask);
            a[i] = hi ? pa - a[i] : a[i] + pa;
            b[i] = hi ? pb - b[i] : b[i] + pb;
        }
    }
}

// ---------------------------------------------------------------------------
// Kernel 0: tf32-round W, pod-interleave M (m = 2*o+p), scatter to frag order
// ---------------------------------------------------------------------------
__global__ void k_pack_w(const float* __restrict__ W) {
    int idx = blockIdx.x * blockDim.x + threadIdx.x;     // 32768
    if (idx >= 32 * 32 * 32) return;
    int lane = idx & 31;
    int mtg  = (idx >> 5) & 31;     // m16 tile over M=512
    int kq   = idx >> 10;           // k8 tile over K=256
    int g = lane >> 2, t = lane & 3;
    int m0 = mtg * 16 + g;          // row g
    int m1 = m0 + 8;                // row g+8
    int k0 = kq * 8 + t;
    float4 f;
    f.x = tf32_round(W[(m0 & 1) * 65536 + (m0 >> 1) * 256 + k0    ]);
    f.y = tf32_round(W[(m1 & 1) * 65536 + (m1 >> 1) * 256 + k0    ]);
    f.z = tf32_round(W[(m0 & 1) * 65536 + (m0 >> 1) * 256 + k0 + 4]);
    f.w = tf32_round(W[(m1 & 1) * 65536 + (m1 >> 1) * 256 + k0 + 4]);
    *reinterpret_cast<float4*>(&g_WtF[(size_t)idx * 4]) = f;
}

// ---------------------------------------------------------------------------
// Kernel 1: forward 2D FWHT (x -> g_f2, tf32-rounded)
// ---------------------------------------------------------------------------
__global__ __launch_bounds__(256) void k_fwht_fwd(const float* __restrict__ x) {
    __shared__ float t[64][65];
    const size_t base = (size_t)blockIdx.x * HW;
    const int tid = threadIdx.x, lane = tid & 31;
    const int sub = tid & 7;
    const int grp = tid >> 3;
    float a[8], b[8];

    {
        const float* r0 = &x[base + grp * 64 + sub * 8];
        const float* r1 = &x[base + (grp + 32) * 64 + sub * 8];
        *reinterpret_cast<float4*>(&a[0]) = *reinterpret_cast<const float4*>(r0);
        *reinterpret_cast<float4*>(&a[4]) = *reinterpret_cast<const float4*>(r0 + 4);
        *reinterpret_cast<float4*>(&b[0]) = *reinterpret_cast<const float4*>(r1);
        *reinterpret_cast<float4*>(&b[4]) = *reinterpret_cast<const float4*>(r1 + 4);
    }
    wht64_vec(a, b, lane);
    #pragma unroll
    for (int i = 0; i < 8; i++) {
        t[grp][sub * 8 + i]      = a[i];
        t[grp + 32][sub * 8 + i] = b[i];
    }
    __syncthreads();

    #pragma unroll
    for (int i = 0; i < 8; i++) {
        a[i] = t[sub * 8 + i][grp];
        b[i] = t[sub * 8 + i][grp + 32];
    }
    wht64_vec(a, b, lane);
    __syncthreads();
    #pragma unroll
    for (int i = 0; i < 8; i++) {
        t[sub * 8 + i][grp]      = a[i];
        t[sub * 8 + i][grp + 32] = b[i];
    }
    __syncthreads();

    #pragma unroll
    for (int i = 0; i < 16; i++) {
        int idx = tid + i * 256;
        g_f2[base + idx] = tf32_round(t[idx >> 6][idx & 63]);
    }
}

// ---------------------------------------------------------------------------
// Kernel 2: fused GEMM (M=512 pod-interleaved) + v-scale + softthr + pod-sum.
// BM=256 x BN=128, warp tile 64x64 (4m x 8n frags), 8 warps (4m x 2n),
// K=256 in 16-chunks, 3-stage cp.async, XOR-swizzled B, LDS.128 A frags.
// ---------------------------------------------------------------------------
#define A_STG 4096                        // floats/stage: 2kq*16mt*32lane*4
#define B_STG 2048                        // floats/stage: 16k * 128n
#define STG   (A_STG + B_STG)             // 6144 floats
#define NSTAGE 3
#define GEMM_SMEM_BYTES (NSTAGE * STG * 4)   // 73728

__device__ __forceinline__ void cp_async16(void* smem, const void* gmem) {
    uint32_t s = (uint32_t)__cvta_generic_to_shared(smem);
    asm volatile("cp.async.ca.shared.global [%0], [%1], 16;\n" :: "r"(s), "l"(gmem));
}

__device__ __forceinline__ void mma_tf32(float& d0, float& d1, float& d2, float& d3,
                                         uint32_t a0, uint32_t a1, uint32_t a2, uint32_t a3,
                                         uint32_t b0, uint32_t b1) {
    asm volatile(
        "mma.sync.aligned.m16n8k8.row.col.f32.tf32.tf32.f32 "
        "{%0,%1,%2,%3}, {%4,%5,%6,%7}, {%8,%9}, {%0,%1,%2,%3};\n"
        : "+f"(d0), "+f"(d1), "+f"(d2), "+f"(d3)
        : "r"(a0), "r"(a1), "r"(a2), "r"(a3), "r"(b0), "r"(b1));
}

__global__ __launch_bounds__(256) void k_gemm_fused(const float* __restrict__ v,
                                                    const float* __restrict__ T) {
    extern __shared__ float smem[];

    const int tid  = threadIdx.x;
    const int warp = tid >> 5;
    const int lane = tid & 31;
    const int g = lane >> 2;
    const int t = lane & 3;
    const int warp_m = warp & 3;     // 4 m-groups of 64 interleaved rows
    const int warp_n = warp >> 2;    // 2 n-groups of 64 cols

    const int n0 = blockIdx.x * 128;       // hw tile
    const int m16base = blockIdx.y * 16;   // m16-tile base (M=512 total)
    const int oblock  = blockIdx.y * 128;  // output-channel base
    const int b  = blockIdx.z;

    const float* f2b = g_f2 + (size_t)b * CH * HW;

    auto prefetch = [&](int kc, int st) {
        // A: 1024 16B units, fragment-linear
        #pragma unroll
        for (int i = 0; i < 4; i++) {
            int u  = i * 256 + tid;
            int qq = u >> 9;
            int r  = u & 511;
            int mm = r >> 5;
            int ln = r & 31;
            const float* src = &g_WtF[(size_t)(((kc * 2 + qq) * 32 + m16base + mm) * 32 + ln) * 4];
            cp_async16(&smem[st * STG + u * 4], src);
        }
        // B: 16 rows x 128 cols, swizzle col ^= (k&3)<<3
        #pragma unroll
        for (int i = 0; i < 2; i++) {
            int u  = i * 256 + tid;
            int kk = u >> 5;
            int c4 = (u & 31) * 4;
            int col = c4 ^ ((kk & 3) << 3);
            cp_async16(&smem[st * STG + A_STG + kk * 128 + col],
                       &f2b[(size_t)(kc * 16 + kk) * HW + n0 + c4]);
        }
        asm volatile("cp.async.commit_group;\n");
    };

    float acc[4][8][4];
    #pragma unroll
    for (int mt = 0; mt < 4; mt++)
        #pragma unroll
        for (int nt = 0; nt < 8; nt++)
            #pragma unroll
            for (int r = 0; r < 4; r++) acc[mt][nt][r] = 0.0f;

    prefetch(0, 0);
    prefetch(1, 1);

    for (int kc = 0; kc < 16; kc++) {
        const int st = kc % NSTAGE;
        __syncthreads();
        if (kc + 2 < 16) prefetch(kc + 2, (kc + 2) % NSTAGE);
        else asm volatile("cp.async.commit_group;\n");
        asm volatile("cp.async.wait_group 2;\n");
        __syncthreads();

        const float* sA = &smem[st * STG];
        const float* sB = &smem[st * STG + A_STG];

        #pragma unroll
        for (int kq = 0; kq < 2; kq++) {
            const int k8 = kq * 8;
            uint32_t bf[8][2];
            #pragma unroll
            for (int nt = 0; nt < 8; nt++) {
                int col = (warp_n * 64 + nt * 8 + g) ^ (t << 3);
                bf[nt][0] = __float_as_uint(sB[(k8 + t) * 128 + col]);
                bf[nt][1] = __float_as_uint(sB[(k8 + t + 4) * 128 + col]);
            }
            #pragma unroll
            for (int mt = 0; mt < 4; mt++) {
                int u = (kq * 16 + warp_m * 4 + mt) * 32 + lane;
                float4 af = *reinterpret_cast<const float4*>(&sA[u * 4]);
                uint32_t a0 = __float_as_uint(af.x);
                uint32_t a1 = __float_as_uint(af.y);
                uint32_t a2 = __float_as_uint(af.z);
                uint32_t a3 = __float_as_uint(af.w);
                #pragma unroll
                for (int nt = 0; nt < 8; nt++)
                    mma_tf32(acc[mt][nt][0], acc[mt][nt][1],
                             acc[mt][nt][2], acc[mt][nt][3],
                             a0, a1, a2, a3, bf[nt][0], bf[nt][1]);
            }
        }
    }

    // Epilogue: thread's pod p = g&1; partner (lane^4) holds the other pod of
    // the same output channel. softthr each, sum via shfl, even-g lanes store.
    float* f6b = g_f6 + (size_t)b * CH * HW;
    const int p = g & 1;
    const bool writer = (p == 0);
    #pragma unroll
    for (int nt = 0; nt < 8; nt++) {
        int hw = n0 + warp_n * 64 + nt * 8 + 2 * t;
        float vv0 = v[p * HW + hw],     vv1 = v[p * HW + hw + 1];
        float tt0 = T[p * HW + hw],     tt1 = T[p * HW + hw + 1];
        #pragma unroll
        for (int mt = 0; mt < 4; mt++) {
            int rbase = warp_m * 64 + mt * 16 + g;   // block-m row (row g)
            float s0 = softthr(vv0 * acc[mt][nt][0], tt0);
            float s1 = softthr(vv1 * acc[mt][nt][1], tt1);
            float s2 = softthr(vv0 * acc[mt][nt][2], tt0);
            float s3 = softthr(vv1 * acc[mt][nt][3], tt1);
            s0 += __shfl_xor_sync(0xffffffffu, s0, 4);
            s1 += __shfl_xor_sync(0xffffffffu, s1, 4);
            s2 += __shfl_xor_sync(0xffffffffu, s2, 4);
            s3 += __shfl_xor_sync(0xffffffffu, s3, 4);
            if (writer) {
                int o0 = oblock + (rbase >> 1);        // rbase even here
                int o1 = o0 + 4;                       // (rbase+8)>>1
                *reinterpret_cast<float2*>(&f6b[(size_t)o0 * HW + hw]) = make_float2(s0, s1);
                *reinterpret_cast<float2*>(&f6b[(size_t)o1 * HW + hw]) = make_float2(s2, s3);
            }
        }
    }
}

// ---------------------------------------------------------------------------
// Kernel 3: inverse 2D FWHT (*1/4096) + residual
// ---------------------------------------------------------------------------
__global__ __launch_bounds__(256) void k_fwht_inv(const float* __restrict__ x,
                                                  float* __restrict__ out) {
    __shared__ float t[64][65];
    const size_t base = (size_t)blockIdx.x * HW;
    const int tid = threadIdx.x, lane = tid & 31;
    const int sub = tid & 7;
    const int grp = tid >> 3;
    float a[8], b[8];

    {
        const float* r0 = &g_f6[base + grp * 64 + sub * 8];
        const float* r1 = &g_f6[base + (grp + 32) * 64 + sub * 8];
        *reinterpret_cast<float4*>(&a[0]) = *reinterpret_cast<const float4*>(r0);
        *reinterpret_cast<float4*>(&a[4]) = *reinterpret_cast<const float4*>(r0 + 4);
        *reinterpret_cast<float4*>(&b[0]) = *reinterpret_cast<const float4*>(r1);
        *reinterpret_cast<float4*>(&b[4]) = *reinterpret_cast<const float4*>(r1 + 4);
    }
    wht64_vec(a, b, lane);
    #pragma unroll
    for (int i = 0; i < 8; i++) {
        t[grp][sub * 8 + i]      = a[i];
        t[grp + 32][sub * 8 + i] = b[i];
    }
    __syncthreads();

    #pragma unroll
    for (int i = 0; i < 8; i++) {
        a[i] = t[sub * 8 + i][grp];
        b[i] = t[sub * 8 + i][grp + 32];
    }
    wht64_vec(a, b, lane);
    __syncthreads();
    #pragma unroll
    for (int i = 0; i < 8; i++) {
        t[sub * 8 + i][grp]      = a[i];
        t[sub * 8 + i][grp + 32] = b[i];
    }
    __syncthreads();

    const float inv = 1.0f / 4096.0f;
    #pragma unroll
    for (int i = 0; i < 16; i++) {
        int idx = tid + i * 256;
        out[base + idx] = fmaf(t[idx >> 6][idx & 63], inv, x[base + idx]);
    }
}

// ---------------------------------------------------------------------------
extern "C" void kernel_launch(void* const* d_in, const int* in_sizes, int n_in,
                              void* d_out, int out_size) {
    const float* x = (const float*)d_in[0];
    const float* v = (const float*)d_in[1];
    const float* W = (const float*)d_in[2];
    const float* T = (const float*)d_in[3];
    float* out = (float*)d_out;

    cudaFuncSetAttribute(k_gemm_fused,
                         cudaFuncAttributeMaxDynamicSharedMemorySize,
                         GEMM_SMEM_BYTES);

    k_pack_w<<<(32 * 32 * 32 + 255) / 256, 256>>>(W);
    k_fwht_fwd<<<NIMG, 256>>>(x);
    dim3 grid(HW / 128, 512 / 256, BATCH);   // (32, 2, 32)
    k_gemm_fused<<<grid, 256, GEMM_SMEM_BYTES>>>(v, T);
    k_fwht_inv<<<NIMG, 256>>>(x, out);
}

// round 13
// speedup vs baseline: 1.0006x; 1.0006x over previous
#include <cuda_runtime.h>
#include <cstdint>

// ---------------------------------------------------------------------------
// x: (32, 256, 64, 64) f32   v: (2, 64, 64)   W: (2, 256, 256)   T: (2, 64, 64)
// out = invWHT( sum_p soft( v_p * (W_p @ WHT(x)), T_p ) ) / 4096 + x
// ---------------------------------------------------------------------------

#define BATCH 32
#define CH    256
#define HW    4096
#define NIMG  (BATCH * CH)

__device__ float g_f2[(size_t)BATCH * CH * HW];   // WHT(x), tf32-rounded
__device__ float g_f6[(size_t)BATCH * CH * HW];   // pod-summed soft-thresholded
// W in tf32, pod-interleaved (m = 2*o + p, M=512), mma fragment order:
//   [kq8(32)][m16tile(32)][lane(32)][4 floats]
__device__ float g_WtF[32 * 32 * 32 * 4];

__device__ __forceinline__ float tf32_round(float v) {
    uint32_t u;
    asm("cvt.rna.tf32.f32 %0, %1;" : "=r"(u) : "f"(v));
    return __uint_as_float(u);
}

__device__ __forceinline__ float softthr(float s, float t) {
    float m = fmaxf(fabsf(s) - t, 0.0f);
    return copysignf(m, s);
}

// ---------------------------------------------------------------------------
// 64-pt WHT, 8 consecutive elements/thread; stages 1,2,4 register-local,
// stages 8,16,32 via shfl.xor masks 1,2,4.
// ---------------------------------------------------------------------------
__device__ __forceinline__ void wht8_local(float (&a)[8]) {
    #pragma unroll
    for (int j = 0; j < 8; j += 2) { float s = a[j] + a[j+1], d = a[j] - a[j+1]; a[j] = s; a[j+1] = d; }
    #pragma unroll
    for (int j0 = 0; j0 < 8; j0 += 4)
        #pragma unroll
        for (int j = j0; j < j0 + 2; j++) { float s = a[j] + a[j+2], d = a[j] - a[j+2]; a[j] = s; a[j+2] = d; }
    #pragma unroll
    for (int j = 0; j < 4; j++) { float s = a[j] + a[j+4], d = a[j] - a[j+4]; a[j] = s; a[j+4] = d; }
}

__device__ __forceinline__ void wht64_vec(float (&a)[8], float (&b)[8], int lane) {
    wht8_local(a);
    wht8_local(b);
    #pragma unroll
    for (int mask = 1; mask <= 4; mask <<= 1) {
        bool hi = (lane & mask) != 0;
        #pragma unroll
        for (int i = 0; i < 8; i++) {
            float pa = __shfl_xor_sync(0xffffffffu, a[i], mask);
            float pb = __shfl_xor_sync(0xffffffffu, b[i], mask);
            a[i] = hi ? pa - a[i] : a[i] + pa;
            b[i] = hi ? pb - b[i] : b[i] + pb;
        }
    }
}

// ---------------------------------------------------------------------------
// Kernel 0: tf32-round W, pod-interleave M (m = 2*o+p), scatter to frag order
// ---------------------------------------------------------------------------
__global__ void k_pack_w(const float* __restrict__ W) {
    int idx = blockIdx.x * blockDim.x + threadIdx.x;     // 32768
    if (idx >= 32 * 32 * 32) return;
    int lane = idx & 31;
    int mtg  = (idx >> 5) & 31;     // m16 tile over M=512
    int kq   = idx >> 10;           // k8 tile over K=256
    int g = lane >> 2, t = lane & 3;
    int m0 = mtg * 16 + g;          // row g
    int m1 = m0 + 8;                // row g+8
    int k0 = kq * 8 + t;
    float4 f;
    f.x = tf32_round(W[(m0 & 1) * 65536 + (m0 >> 1) * 256 + k0    ]);
    f.y = tf32_round(W[(m1 & 1) * 65536 + (m1 >> 1) * 256 + k0    ]);
    f.z = tf32_round(W[(m0 & 1) * 65536 + (m0 >> 1) * 256 + k0 + 4]);
    f.w = tf32_round(W[(m1 & 1) * 65536 + (m1 >> 1) * 256 + k0 + 4]);
    *reinterpret_cast<float4*>(&g_WtF[(size_t)idx * 4]) = f;
}

// ---------------------------------------------------------------------------
// Kernel 1: forward 2D FWHT (x -> g_f2, tf32-rounded)
// ---------------------------------------------------------------------------
__global__ __launch_bounds__(256) void k_fwht_fwd(const float* __restrict__ x) {
    __shared__ float t[64][65];
    const size_t base = (size_t)blockIdx.x * HW;
    const int tid = threadIdx.x, lane = tid & 31;
    const int sub = tid & 7;
    const int grp = tid >> 3;
    float a[8], b[8];

    {
        const float* r0 = &x[base + grp * 64 + sub * 8];
        const float* r1 = &x[base + (grp + 32) * 64 + sub * 8];
        *reinterpret_cast<float4*>(&a[0]) = *reinterpret_cast<const float4*>(r0);
        *reinterpret_cast<float4*>(&a[4]) = *reinterpret_cast<const float4*>(r0 + 4);
        *reinterpret_cast<float4*>(&b[0]) = *reinterpret_cast<const float4*>(r1);
        *reinterpret_cast<float4*>(&b[4]) = *reinterpret_cast<const float4*>(r1 + 4);
    }
    wht64_vec(a, b, lane);
    #pragma unroll
    for (int i = 0; i < 8; i++) {
        t[grp][sub * 8 + i]      = a[i];
        t[grp + 32][sub * 8 + i] = b[i];
    }
    __syncthreads();

    #pragma unroll
    for (int i = 0; i < 8; i++) {
        a[i] = t[sub * 8 + i][grp];
        b[i] = t[sub * 8 + i][grp + 32];
    }
    wht64_vec(a, b, lane);
    __syncthreads();
    #pragma unroll
    for (int i = 0; i < 8; i++) {
        t[sub * 8 + i][grp]      = a[i];
        t[sub * 8 + i][grp + 32] = b[i];
    }
    __syncthreads();

    #pragma unroll
    for (int i = 0; i < 16; i++) {
        int idx = tid + i * 256;
        g_f2[base + idx] = tf32_round(t[idx >> 6][idx & 63]);
    }
}

// ---------------------------------------------------------------------------
// Kernel 2: fused GEMM (M=512 pod-interleaved) + v-scale + softthr + pod-sum.
// BM=256 x BN=128, warp tile 64x64 (4m x 8n frags), 8 warps (4m x 2n),
// K=256 in 16-chunks, 3-stage cp.async, XOR-swizzled B, LDS.128 A frags.
// ---------------------------------------------------------------------------
#define A_STG 4096                        // floats/stage: 2kq*16mt*32lane*4
#define B_STG 2048                        // floats/stage: 16k * 128n
#define STG   (A_STG + B_STG)             // 6144 floats
#define NSTAGE 3
#define GEMM_SMEM_BYTES (NSTAGE * STG * 4)   // 73728

__device__ __forceinline__ void cp_async16(void* smem, const void* gmem) {
    uint32_t s = (uint32_t)__cvta_generic_to_shared(smem);
    asm volatile("cp.async.ca.shared.global [%0], [%1], 16;\n" :: "r"(s), "l"(gmem));
}

__device__ __forceinline__ void mma_tf32(float& d0, float& d1, float& d2, float& d3,
                                         uint32_t a0, uint32_t a1, uint32_t a2, uint32_t a3,
                                         uint32_t b0, uint32_t b1) {
    asm volatile(
        "mma.sync.aligned.m16n8k8.row.col.f32.tf32.tf32.f32 "
        "{%0,%1,%2,%3}, {%4,%5,%6,%7}, {%8,%9}, {%0,%1,%2,%3};\n"
        : "+f"(d0), "+f"(d1), "+f"(d2), "+f"(d3)
        : "r"(a0), "r"(a1), "r"(a2), "r"(a3), "r"(b0), "r"(b1));
}

__global__ __launch_bounds__(256) void k_gemm_fused(const float* __restrict__ v,
                                                    const float* __restrict__ T) {
    extern __shared__ float smem[];

    const int tid  = threadIdx.x;
    const int warp = tid >> 5;
    const int lane = tid & 31;
    const int g = lane >> 2;
    const int t = lane & 3;
    const int warp_m = warp & 3;     // 4 m-groups of 64 interleaved rows
    const int warp_n = warp >> 2;    // 2 n-groups of 64 cols

    const int n0 = blockIdx.x * 128;       // hw tile
    const int m16base = blockIdx.y * 16;   // m16-tile base (M=512 total)
    const int oblock  = blockIdx.y * 128;  // output-channel base
    const int b  = blockIdx.z;

    const float* f2b = g_f2 + (size_t)b * CH * HW;

    auto prefetch = [&](int kc, int st) {
        // A: 1024 16B units, fragment-linear
        #pragma unroll
        for (int i = 0; i < 4; i++) {
            int u  = i * 256 + tid;
            int qq = u >> 9;
            int r  = u & 511;
            int mm = r >> 5;
            int ln = r & 31;
            const float* src = &g_WtF[(size_t)(((kc * 2 + qq) * 32 + m16base + mm) * 32 + ln) * 4];
            cp_async16(&smem[st * STG + u * 4], src);
        }
        // B: 16 rows x 128 cols, swizzle col ^= (k&3)<<3
        #pragma unroll
        for (int i = 0; i < 2; i++) {
            int u  = i * 256 + tid;
            int kk = u >> 5;
            int c4 = (u & 31) * 4;
            int col = c4 ^ ((kk & 3) << 3);
            cp_async16(&smem[st * STG + A_STG + kk * 128 + col],
                       &f2b[(size_t)(kc * 16 + kk) * HW + n0 + c4]);
        }
        asm volatile("cp.async.commit_group;\n");
    };

    float acc[4][8][4];
    #pragma unroll
    for (int mt = 0; mt < 4; mt++)
        #pragma unroll
        for (int nt = 0; nt < 8; nt++)
            #pragma unroll
            for (int r = 0; r < 4; r++) acc[mt][nt][r] = 0.0f;

    prefetch(0, 0);
    prefetch(1, 1);

    for (int kc = 0; kc < 16; kc++) {
        const int st = kc % NSTAGE;
        __syncthreads();
        if (kc + 2 < 16) prefetch(kc + 2, (kc + 2) % NSTAGE);
        else asm volatile("cp.async.commit_group;\n");
        asm volatile("cp.async.wait_group 2;\n");
        __syncthreads();

        const float* sA = &smem[st * STG];
        const float* sB = &smem[st * STG + A_STG];

        #pragma unroll
        for (int kq = 0; kq < 2; kq++) {
            const int k8 = kq * 8;
            uint32_t bf[8][2];
            #pragma unroll
            for (int nt = 0; nt < 8; nt++) {
                int col = (warp_n * 64 + nt * 8 + g) ^ (t << 3);
                bf[nt][0] = __float_as_uint(sB[(k8 + t) * 128 + col]);
                bf[nt][1] = __float_as_uint(sB[(k8 + t + 4) * 128 + col]);
            }
            #pragma unroll
            for (int mt = 0; mt < 4; mt++) {
                int u = (kq * 16 + warp_m * 4 + mt) * 32 + lane;
                float4 af = *reinterpret_cast<const float4*>(&sA[u * 4]);
                uint32_t a0 = __float_as_uint(af.x);
                uint32_t a1 = __float_as_uint(af.y);
                uint32_t a2 = __float_as_uint(af.z);
                uint32_t a3 = __float_as_uint(af.w);
                #pragma unroll
                for (int nt = 0; nt < 8; nt++)
                    mma_tf32(acc[mt][nt][0], acc[mt][nt][1],
                             acc[mt][nt][2], acc[mt][nt][3],
                             a0, a1, a2, a3, bf[nt][0], bf[nt][1]);
            }
        }
    }

    // Epilogue: thread's pod p = g&1; partner (lane^4) holds the other pod of
    // the same output channel. softthr each, sum via shfl, even-g lanes store.
    float* f6b = g_f6 + (size_t)b * CH * HW;
    const int p = g & 1;
    const bool writer = (p == 0);
    #pragma unroll
    for (int nt = 0; nt < 8; nt++) {
        int hw = n0 + warp_n * 64 + nt * 8 + 2 * t;
        float vv0 = v[p * HW + hw],     vv1 = v[p * HW + hw + 1];
        float tt0 = T[p * HW + hw],     tt1 = T[p * HW + hw + 1];
        #pragma unroll
        for (int mt = 0; mt < 4; mt++) {
            int rbase = warp_m * 64 + mt * 16 + g;   // block-m row (row g)
            float s0 = softthr(vv0 * acc[mt][nt][0], tt0);
            float s1 = softthr(vv1 * acc[mt][nt][1], tt1);
            float s2 = softthr(vv0 * acc[mt][nt][2], tt0);
            float s3 = softthr(vv1 * acc[mt][nt][3], tt1);
            s0 += __shfl_xor_sync(0xffffffffu, s0, 4);
            s1 += __shfl_xor_sync(0xffffffffu, s1, 4);
            s2 += __shfl_xor_sync(0xffffffffu, s2, 4);
            s3 += __shfl_xor_sync(0xffffffffu, s3, 4);
            if (writer) {
                int o0 = oblock + (rbase >> 1);        // rbase even here
                int o1 = o0 + 4;                       // (rbase+8)>>1
                *reinterpret_cast<float2*>(&f6b[(size_t)o0 * HW + hw]) = make_float2(s0, s1);
                *reinterpret_cast<float2*>(&f6b[(size_t)o1 * HW + hw]) = make_float2(s2, s3);
            }
        }
    }
}

// ---------------------------------------------------------------------------
// Kernel 3: inverse 2D FWHT (*1/4096) + residual
// ---------------------------------------------------------------------------
__global__ __launch_bounds__(256) void k_fwht_inv(const float* __restrict__ x,
                                                  float* __restrict__ out) {
    __shared__ float t[64][65];
    const size_t base = (size_t)blockIdx.x * HW;
    const int tid = threadIdx.x, lane = tid & 31;
    const int sub = tid & 7;
    const int grp = tid >> 3;
    float a[8], b[8];

    {
        const float* r0 = &g_f6[base + grp * 64 + sub * 8];
        const float* r1 = &g_f6[base + (grp + 32) * 64 + sub * 8];
        *reinterpret_cast<float4*>(&a[0]) = *reinterpret_cast<const float4*>(r0);
        *reinterpret_cast<float4*>(&a[4]) = *reinterpret_cast<const float4*>(r0 + 4);
        *reinterpret_cast<float4*>(&b[0]) = *reinterpret_cast<const float4*>(r1);
        *reinterpret_cast<float4*>(&b[4]) = *reinterpret_cast<const float4*>(r1 + 4);
    }
    wht64_vec(a, b, lane);
    #pragma unroll
    for (int i = 0; i < 8; i++) {
        t[grp][sub * 8 + i]      = a[i];
        t[grp + 32][sub * 8 + i] = b[i];
    }
    __syncthreads();

    #pragma unroll
    for (int i = 0; i < 8; i++) {
        a[i] = t[sub * 8 + i][grp];
        b[i] = t[sub * 8 + i][grp + 32];
    }
    wht64_vec(a, b, lane);
    __syncthreads();
    #pragma unroll
    for (int i = 0; i < 8; i++) {
        t[sub * 8 + i][grp]      = a[i];
        t[sub * 8 + i][grp + 32] = b[i];
    }
    __syncthreads();

    const float inv = 1.0f / 4096.0f;
    #pragma unroll
    for (int i = 0; i < 16; i++) {
        int idx = tid + i * 256;
        out[base + idx] = fmaf(t[idx >> 6][idx & 63], inv, x[base + idx]);
    }
}

// ---------------------------------------------------------------------------
extern "C" void kernel_launch(void* const* d_in, const int* in_sizes, int n_in,
                              void* d_out, int out_size) {
    const float* x = (const float*)d_in[0];
    const float* v = (const float*)d_in[1];
    const float* W = (const float*)d_in[2];
    const float* T = (const float*)d_in[3];
    float* out = (float*)d_out;

    cudaFuncSetAttribute(k_gemm_fused,
                         cudaFuncAttributeMaxDynamicSharedMemorySize,
                         GEMM_SMEM_BYTES);

    k_pack_w<<<(32 * 32 * 32 + 255) / 256, 256>>>(W);
    k_fwht_fwd<<<NIMG, 256>>>(x);
    dim3 grid(HW / 128, 512 / 256, BATCH);   // (32, 2, 32)
    k_gemm_fused<<<grid, 256, GEMM_SMEM_BYTES>>>(v, T);
    k_fwht_inv<<<NIMG, 256>>>(x, out);
}

// round 14
// speedup vs baseline: 1.4090x; 1.4082x over previous
#include <cuda_runtime.h>
#include <cuda_fp16.h>
#include <cstdint>

// ---------------------------------------------------------------------------
// x: (32, 256, 64, 64) f32   v: (2, 64, 64)   W: (2, 256, 256)   T: (2, 64, 64)
// out = invWHT( sum_p soft( v_p * (W_p @ WHT(x)), T_p ) ) / 4096 + x
// GEMM in fp16 (m16n8k16, fp32 accumulate).
// ---------------------------------------------------------------------------

#define BATCH 32
#define CH    256
#define HW    4096
#define NIMG  (BATCH * CH)

// f2 as half2, channel-pair interleaved: [b][c/2][hw] -> half2(c_even, c_odd)
__device__ uint32_t g_f2p[(size_t)BATCH * (CH / 2) * HW];     // 64 MB
__device__ float    g_f6[(size_t)BATCH * CH * HW];            // 128 MB
// W fp16 in m16n8k16 A-fragment order: [pod(2)][kc16(16)][mtile(16)][lane(32)] x uint4
__device__ uint4    g_WtFh[2 * 16 * 16 * 32];

__device__ __forceinline__ float softthr(float s, float t) {
    float m = fmaxf(fabsf(s) - t, 0.0f);
    return copysignf(m, s);
}

// ---------------------------------------------------------------------------
// 64-pt WHT, 8 consecutive elements/thread; stages 1,2,4 register-local,
// stages 8,16,32 via shfl.xor masks 1,2,4.
// ---------------------------------------------------------------------------
__device__ __forceinline__ void wht8_local(float (&a)[8]) {
    #pragma unroll
    for (int j = 0; j < 8; j += 2) { float s = a[j] + a[j+1], d = a[j] - a[j+1]; a[j] = s; a[j+1] = d; }
    #pragma unroll
    for (int j0 = 0; j0 < 8; j0 += 4)
        #pragma unroll
        for (int j = j0; j < j0 + 2; j++) { float s = a[j] + a[j+2], d = a[j] - a[j+2]; a[j] = s; a[j+2] = d; }
    #pragma unroll
    for (int j = 0; j < 4; j++) { float s = a[j] + a[j+4], d = a[j] - a[j+4]; a[j] = s; a[j+4] = d; }
}

__device__ __forceinline__ void wht64_vec(float (&a)[8], float (&b)[8], int lane) {
    wht8_local(a);
    wht8_local(b);
    #pragma unroll
    for (int mask = 1; mask <= 4; mask <<= 1) {
        bool hi = (lane & mask) != 0;
        #pragma unroll
        for (int i = 0; i < 8; i++) {
            float pa = __shfl_xor_sync(0xffffffffu, a[i], mask);
            float pb = __shfl_xor_sync(0xffffffffu, b[i], mask);
            a[i] = hi ? pa - a[i] : a[i] + pa;
            b[i] = hi ? pb - b[i] : b[i] + pb;
        }
    }
}

// ---------------------------------------------------------------------------
// Kernel 0: W -> fp16 m16n8k16 A-fragment order.
// a0={A[g][2t],A[g][2t+1]} a1={A[g+8][..]} a2={A[g][2t+8..9]} a3={A[g+8][2t+8..9]}
// ---------------------------------------------------------------------------
__global__ void k_pack_w(const float* __restrict__ W) {
    int idx = blockIdx.x * blockDim.x + threadIdx.x;   // [p][kc][mtile][lane]
    if (idx >= 2 * 16 * 16 * 32) return;
    int lane = idx & 31;
    int mt   = (idx >> 5) & 15;
    int kc   = (idx >> 9) & 15;
    int p    = idx >> 13;
    int g = lane >> 2, t = lane & 3;
    const float* Wp = W + p * 65536;
    int m0 = mt * 16 + g, m1 = m0 + 8;
    int k0 = kc * 16 + 2 * t;
    __half2 r0 = __floats2half2_rn(Wp[m0 * 256 + k0],     Wp[m0 * 256 + k0 + 1]);
    __half2 r1 = __floats2half2_rn(Wp[m1 * 256 + k0],     Wp[m1 * 256 + k0 + 1]);
    __half2 r2 = __floats2half2_rn(Wp[m0 * 256 + k0 + 8], Wp[m0 * 256 + k0 + 9]);
    __half2 r3 = __floats2half2_rn(Wp[m1 * 256 + k0 + 8], Wp[m1 * 256 + k0 + 9]);
    uint4 u;
    u.x = *reinterpret_cast<uint32_t*>(&r0);
    u.y = *reinterpret_cast<uint32_t*>(&r1);
    u.z = *reinterpret_cast<uint32_t*>(&r2);
    u.w = *reinterpret_cast<uint32_t*>(&r3);
    g_WtFh[idx] = u;
}

// ---------------------------------------------------------------------------
// Kernel 1: forward 2D FWHT on a CHANNEL PAIR -> g_f2p half2-interleaved.
// Block handles channels (2j, 2j+1) of batch b; two smem tiles.
// ---------------------------------------------------------------------------
__global__ __launch_bounds__(256) void k_fwht_fwd(const float* __restrict__ x) {
    __shared__ float t0[64][65];
    __shared__ float t1[64][65];
    const size_t base0 = (size_t)blockIdx.x * 2 * HW;   // channel 2j
    const int tid = threadIdx.x, lane = tid & 31;
    const int sub = tid & 7;
    const int grp = tid >> 3;
    float a[8], b[8];

    #pragma unroll
    for (int img = 0; img < 2; img++) {
        const float* xi = &x[base0 + (size_t)img * HW];
        float (*tt)[65] = img ? t1 : t0;
        {
            const float* r0 = &xi[grp * 64 + sub * 8];
            const float* r1 = &xi[(grp + 32) * 64 + sub * 8];
            *reinterpret_cast<float4*>(&a[0]) = *reinterpret_cast<const float4*>(r0);
            *reinterpret_cast<float4*>(&a[4]) = *reinterpret_cast<const float4*>(r0 + 4);
            *reinterpret_cast<float4*>(&b[0]) = *reinterpret_cast<const float4*>(r1);
            *reinterpret_cast<float4*>(&b[4]) = *reinterpret_cast<const float4*>(r1 + 4);
        }
        wht64_vec(a, b, lane);
        #pragma unroll
        for (int i = 0; i < 8; i++) {
            tt[grp][sub * 8 + i]      = a[i];
            tt[grp + 32][sub * 8 + i] = b[i];
        }
        __syncthreads();
        #pragma unroll
        for (int i = 0; i < 8; i++) {
            a[i] = tt[sub * 8 + i][grp];
            b[i] = tt[sub * 8 + i][grp + 32];
        }
        wht64_vec(a, b, lane);
        __syncthreads();
        #pragma unroll
        for (int i = 0; i < 8; i++) {
            tt[sub * 8 + i][grp]      = a[i];
            tt[sub * 8 + i][grp + 32] = b[i];
        }
        __syncthreads();
    }

    // interleaved half2 write: lo = even channel, hi = odd channel
    uint32_t* dst = &g_f2p[(size_t)blockIdx.x * HW];
    #pragma unroll
    for (int i = 0; i < 16; i++) {
        int idx = tid + i * 256;
        __half2 h = __floats2half2_rn(t0[idx >> 6][idx & 63], t1[idx >> 6][idx & 63]);
        dst[idx] = *reinterpret_cast<uint32_t*>(&h);
    }
}

// ---------------------------------------------------------------------------
// Kernel 2: fused dual-pod fp16 GEMM + v-scale + softthr + pod-sum.
// BM=128 x BN=64, warp 32x32, K=256 in 16-chunks (one m16n8k16 per k-chunk
// per frag), 3-stage cp.async, XOR-swizzled B, LDS.128 A frags.
// ---------------------------------------------------------------------------
#define A_STG 2048                        // floats/stage: 512 uint4 = 8KB
#define B_STG 512                         // floats/stage: 8 cpair * 64 half2 = 2KB
#define STG   (A_STG + B_STG)             // 2560 floats = 10KB
#define NSTAGE 3
#define GEMM_SMEM_BYTES (NSTAGE * STG * 4)   // 30720

__device__ __forceinline__ void cp_async16(void* smem, const void* gmem) {
    uint32_t s = (uint32_t)__cvta_generic_to_shared(smem);
    asm volatile("cp.async.ca.shared.global [%0], [%1], 16;\n" :: "r"(s), "l"(gmem));
}

__device__ __forceinline__ void mma_f16(float& d0, float& d1, float& d2, float& d3,
                                        uint32_t a0, uint32_t a1, uint32_t a2, uint32_t a3,
                                        uint32_t b0, uint32_t b1) {
    asm volatile(
        "mma.sync.aligned.m16n8k16.row.col.f32.f16.f16.f32 "
        "{%0,%1,%2,%3}, {%4,%5,%6,%7}, {%8,%9}, {%0,%1,%2,%3};\n"
        : "+f"(d0), "+f"(d1), "+f"(d2), "+f"(d3)
        : "r"(a0), "r"(a1), "r"(a2), "r"(a3), "r"(b0), "r"(b1));
}

__global__ __launch_bounds__(256) void k_gemm_fused(const float* __restrict__ v,
                                                    const float* __restrict__ T) {
    extern __shared__ float smem[];

    const int tid  = threadIdx.x;
    const int warp = tid >> 5;
    const int lane = tid & 31;
    const int g = lane >> 2;
    const int t = lane & 3;
    const int warp_m = warp & 3;
    const int warp_n = warp >> 2;

    const int n0 = blockIdx.x * 64;
    const int m0 = blockIdx.y * 128;
    const int m16base = blockIdx.y * 8;
    const int b  = blockIdx.z;

    const uint32_t* f2b = g_f2p + (size_t)b * (CH / 2) * HW;

    auto prefetch = [&](int kc, int st) {
        // A: 512 uint4 units, fragment-linear [p][mtile(8)][lane]
        #pragma unroll
        for (int i = 0; i < 2; i++) {
            int u  = i * 256 + tid;
            int p  = u >> 8;
            int mm = (u >> 5) & 7;
            int ln = u & 31;
            const uint4* src = &g_WtFh[((p * 16 + kc) * 16 + m16base + mm) * 32 + ln];
            cp_async16(&smem[st * STG + u * 4], src);
        }
        // B: 8 cpair rows x 64 half2 cols; swizzle phys_n4chunk ^= (cpair&3)<<3
        if (tid < 128) {
            int kk = tid >> 4;                 // cpair 0..7
            int c4 = (tid & 15) * 4;           // n chunk of 4 half2
            int phys = c4 ^ ((kk & 3) << 3);
            cp_async16(&smem[st * STG + A_STG + kk * 64 + phys],
                       &f2b[(size_t)(kc * 8 + kk) * HW + n0 + c4]);
        }
        asm volatile("cp.async.commit_group;\n");
    };

    float acc[2][2][4][4];
    #pragma unroll
    for (int p = 0; p < 2; p++)
        #pragma unroll
        for (int mt = 0; mt < 2; mt++)
            #pragma unroll
            for (int nt = 0; nt < 4; nt++)
                #pragma unroll
                for (int r = 0; r < 4; r++) acc[p][mt][nt][r] = 0.0f;

    prefetch(0, 0);
    prefetch(1, 1);

    for (int kc = 0; kc < 16; kc++) {
        const int st = kc % NSTAGE;
        __syncthreads();
        if (kc + 2 < 16) prefetch(kc + 2, (kc + 2) % NSTAGE);
        else asm volatile("cp.async.commit_group;\n");
        asm volatile("cp.async.wait_group 2;\n");
        __syncthreads();

        const uint32_t* sA = reinterpret_cast<const uint32_t*>(&smem[st * STG]);
        const uint32_t* sB = reinterpret_cast<const uint32_t*>(&smem[st * STG + A_STG]);

        // B fragments: b0 = cpair t, b1 = cpair t+4, col n ^ (t<<3) (conflict-free)
        uint32_t bf[4][2];
        #pragma unroll
        for (int nt = 0; nt < 4; nt++) {
            int n = warp_n * 32 + nt * 8 + g;
            int col = n ^ (t << 3);
            bf[nt][0] = sB[t * 64 + col];
            bf[nt][1] = sB[(t + 4) * 64 + col];
        }
        #pragma unroll
        for (int p = 0; p < 2; p++) {
            #pragma unroll
            for (int mt = 0; mt < 2; mt++) {
                int u = (p * 8 + warp_m * 2 + mt) * 32 + lane;
                uint4 af = reinterpret_cast<const uint4*>(sA)[u];
                #pragma unroll
                for (int nt = 0; nt < 4; nt++)
                    mma_f16(acc[p][mt][nt][0], acc[p][mt][nt][1],
                            acc[p][mt][nt][2], acc[p][mt][nt][3],
                            af.x, af.y, af.z, af.w, bf[nt][0], bf[nt][1]);
            }
        }
    }

    // Epilogue: v-scale, soft-threshold, sum pods
    float* f6b = g_f6 + (size_t)b * CH * HW;
    #pragma unroll
    for (int nt = 0; nt < 4; nt++) {
        int hw = n0 + warp_n * 32 + nt * 8 + 2 * t;
        float v0[2], v1[2], t0[2], t1[2];
        #pragma unroll
        for (int p = 0; p < 2; p++) {
            v0[p] = v[p * HW + hw];
            v1[p] = v[p * HW + hw + 1];
            t0[p] = T[p * HW + hw];
            t1[p] = T[p * HW + hw + 1];
        }
        #pragma unroll
        for (int mt = 0; mt < 2; mt++) {
            int o0 = m0 + warp_m * 32 + mt * 16 + g;
            float2 lo = make_float2(0.f, 0.f);
            float2 hi = make_float2(0.f, 0.f);
            #pragma unroll
            for (int p = 0; p < 2; p++) {
                lo.x += softthr(v0[p] * acc[p][mt][nt][0], t0[p]);
                lo.y += softthr(v1[p] * acc[p][mt][nt][1], t1[p]);
                hi.x += softthr(v0[p] * acc[p][mt][nt][2], t0[p]);
                hi.y += softthr(v1[p] * acc[p][mt][nt][3], t1[p]);
            }
            *reinterpret_cast<float2*>(&f6b[(size_t)o0 * HW + hw]) = lo;
            *reinterpret_cast<float2*>(&f6b[(size_t)(o0 + 8) * HW + hw]) = hi;
        }
    }
}

// ---------------------------------------------------------------------------
// Kernel 3: inverse 2D FWHT (*1/4096) + residual
// ---------------------------------------------------------------------------
__global__ __launch_bounds__(256) void k_fwht_inv(const float* __restrict__ x,
                                                  float* __restrict__ out) {
    __shared__ float t[64][65];
    const size_t base = (size_t)blockIdx.x * HW;
    const int tid = threadIdx.x, lane = tid & 31;
    const int sub = tid & 7;
    const int grp = tid >> 3;
    float a[8], b[8];

    {
        const float* r0 = &g_f6[base + grp * 64 + sub * 8];
        const float* r1 = &g_f6[base + (grp + 32) * 64 + sub * 8];
        *reinterpret_cast<float4*>(&a[0]) = *reinterpret_cast<const float4*>(r0);
        *reinterpret_cast<float4*>(&a[4]) = *reinterpret_cast<const float4*>(r0 + 4);
        *reinterpret_cast<float4*>(&b[0]) = *reinterpret_cast<const float4*>(r1);
        *reinterpret_cast<float4*>(&b[4]) = *reinterpret_cast<const float4*>(r1 + 4);
    }
    wht64_vec(a, b, lane);
    #pragma unroll
    for (int i = 0; i < 8; i++) {
        t[grp][sub * 8 + i]      = a[i];
        t[grp + 32][sub * 8 + i] = b[i];
    }
    __syncthreads();

    #pragma unroll
    for (int i = 0; i < 8; i++) {
        a[i] = t[sub * 8 + i][grp];
        b[i] = t[sub * 8 + i][grp + 32];
    }
    wht64_vec(a, b, lane);
    __syncthreads();
    #pragma unroll
    for (int i = 0; i < 8; i++) {
        t[sub * 8 + i][grp]      = a[i];
        t[sub * 8 + i][grp + 32] = b[i];
    }
    __syncthreads();

    const float inv = 1.0f / 4096.0f;
    #pragma unroll
    for (int i = 0; i < 16; i++) {
        int idx = tid + i * 256;
        out[base + idx] = fmaf(t[idx >> 6][idx & 63], inv, x[base + idx]);
    }
}

// ---------------------------------------------------------------------------
extern "C" void kernel_launch(void* const* d_in, const int* in_sizes, int n_in,
                              void* d_out, int out_size) {
    const float* x = (const float*)d_in[0];
    const float* v = (const float*)d_in[1];
    const float* W = (const float*)d_in[2];
    const float* T = (const float*)d_in[3];
    float* out = (float*)d_out;

    cudaFuncSetAttribute(k_gemm_fused,
                         cudaFuncAttributeMaxDynamicSharedMemorySize,
                         GEMM_SMEM_BYTES);

    k_pack_w<<<(2 * 16 * 16 * 32 + 255) / 256, 256>>>(W);
    k_fwht_fwd<<<NIMG / 2, 256>>>(x);
    dim3 grid(HW / 64, CH / 128, BATCH);   // (64, 2, 32)
    k_gemm_fused<<<grid, 256, GEMM_SMEM_BYTES>>>(v, T);
    k_fwht_inv<<<NIMG, 256>>>(x, out);
}

// round 15
// speedup vs baseline: 1.4504x; 1.0293x over previous
#include <cuda_runtime.h>
#include <cuda_fp16.h>
#include <cstdint>

// ---------------------------------------------------------------------------
// x: (32, 256, 64, 64) f32   v: (2, 64, 64)   W: (2, 256, 256)   T: (2, 64, 64)
// out = invWHT( sum_p soft( v_p * (W_p @ WHT(x)), T_p ) ) / 4096 + x
// GEMM fp16 (m16n8k16, fp32 acc); f2 and f6 both stored as packed half2.
// ---------------------------------------------------------------------------

#define BATCH 32
#define CH    256
#define HW    4096
#define NIMG  (BATCH * CH)

// f2 as half2, channel-pair interleaved: [b][c/2][hw] -> half2(c_even, c_odd)
__device__ uint32_t g_f2p[(size_t)BATCH * (CH / 2) * HW];     // 64 MB
// f6 as half2, pair (c, c+8) within each 16-row tile: [b][pc][hw],
//   pc = (c>>4)*8 + (c&7), pair = (c, c+8)
__device__ uint32_t g_f6h[(size_t)BATCH * (CH / 2) * HW];     // 64 MB
// W fp16 in m16n8k16 A-fragment order: [pod(2)][kc16(16)][mtile(16)][lane(32)] x uint4
__device__ uint4    g_WtFh[2 * 16 * 16 * 32];

__device__ __forceinline__ float softthr(float s, float t) {
    float m = fmaxf(fabsf(s) - t, 0.0f);
    return copysignf(m, s);
}

// ---------------------------------------------------------------------------
// 64-pt WHT, 8 consecutive elements/thread; stages 1,2,4 register-local,
// stages 8,16,32 via shfl.xor masks 1,2,4.
// ---------------------------------------------------------------------------
__device__ __forceinline__ void wht8_local(float (&a)[8]) {
    #pragma unroll
    for (int j = 0; j < 8; j += 2) { float s = a[j] + a[j+1], d = a[j] - a[j+1]; a[j] = s; a[j+1] = d; }
    #pragma unroll
    for (int j0 = 0; j0 < 8; j0 += 4)
        #pragma unroll
        for (int j = j0; j < j0 + 2; j++) { float s = a[j] + a[j+2], d = a[j] - a[j+2]; a[j] = s; a[j+2] = d; }
    #pragma unroll
    for (int j = 0; j < 4; j++) { float s = a[j] + a[j+4], d = a[j] - a[j+4]; a[j] = s; a[j+4] = d; }
}

__device__ __forceinline__ void wht64_vec(float (&a)[8], float (&b)[8], int lane) {
    wht8_local(a);
    wht8_local(b);
    #pragma unroll
    for (int mask = 1; mask <= 4; mask <<= 1) {
        bool hi = (lane & mask) != 0;
        #pragma unroll
        for (int i = 0; i < 8; i++) {
            float pa = __shfl_xor_sync(0xffffffffu, a[i], mask);
            float pb = __shfl_xor_sync(0xffffffffu, b[i], mask);
            a[i] = hi ? pa - a[i] : a[i] + pa;
            b[i] = hi ? pb - b[i] : b[i] + pb;
        }
    }
}

// ---------------------------------------------------------------------------
// Kernel 0: W -> fp16 m16n8k16 A-fragment order.
// ---------------------------------------------------------------------------
__global__ void k_pack_w(const float* __restrict__ W) {
    int idx = blockIdx.x * blockDim.x + threadIdx.x;   // [p][kc][mtile][lane]
    if (idx >= 2 * 16 * 16 * 32) return;
    int lane = idx & 31;
    int mt   = (idx >> 5) & 15;
    int kc   = (idx >> 9) & 15;
    int p    = idx >> 13;
    int g = lane >> 2, t = lane & 3;
    const float* Wp = W + p * 65536;
    int m0 = mt * 16 + g, m1 = m0 + 8;
    int k0 = kc * 16 + 2 * t;
    __half2 r0 = __floats2half2_rn(Wp[m0 * 256 + k0],     Wp[m0 * 256 + k0 + 1]);
    __half2 r1 = __floats2half2_rn(Wp[m1 * 256 + k0],     Wp[m1 * 256 + k0 + 1]);
    __half2 r2 = __floats2half2_rn(Wp[m0 * 256 + k0 + 8], Wp[m0 * 256 + k0 + 9]);
    __half2 r3 = __floats2half2_rn(Wp[m1 * 256 + k0 + 8], Wp[m1 * 256 + k0 + 9]);
    uint4 u;
    u.x = *reinterpret_cast<uint32_t*>(&r0);
    u.y = *reinterpret_cast<uint32_t*>(&r1);
    u.z = *reinterpret_cast<uint32_t*>(&r2);
    u.w = *reinterpret_cast<uint32_t*>(&r3);
    g_WtFh[idx] = u;
}

// ---------------------------------------------------------------------------
// Kernel 1: forward 2D FWHT on a CHANNEL PAIR -> g_f2p half2-interleaved.
// ---------------------------------------------------------------------------
__global__ __launch_bounds__(256) void k_fwht_fwd(const float* __restrict__ x) {
    __shared__ float t0[64][65];
    __shared__ float t1[64][65];
    const size_t base0 = (size_t)blockIdx.x * 2 * HW;
    const int tid = threadIdx.x, lane = tid & 31;
    const int sub = tid & 7;
    const int grp = tid >> 3;
    float a[8], b[8];

    #pragma unroll
    for (int img = 0; img < 2; img++) {
        const float* xi = &x[base0 + (size_t)img * HW];
        float (*tt)[65] = img ? t1 : t0;
        {
            const float* r0 = &xi[grp * 64 + sub * 8];
            const float* r1 = &xi[(grp + 32) * 64 + sub * 8];
            *reinterpret_cast<float4*>(&a[0]) = *reinterpret_cast<const float4*>(r0);
            *reinterpret_cast<float4*>(&a[4]) = *reinterpret_cast<const float4*>(r0 + 4);
            *reinterpret_cast<float4*>(&b[0]) = *reinterpret_cast<const float4*>(r1);
            *reinterpret_cast<float4*>(&b[4]) = *reinterpret_cast<const float4*>(r1 + 4);
        }
        wht64_vec(a, b, lane);
        #pragma unroll
        for (int i = 0; i < 8; i++) {
            tt[grp][sub * 8 + i]      = a[i];
            tt[grp + 32][sub * 8 + i] = b[i];
        }
        __syncthreads();
        #pragma unroll
        for (int i = 0; i < 8; i++) {
            a[i] = tt[sub * 8 + i][grp];
            b[i] = tt[sub * 8 + i][grp + 32];
        }
        wht64_vec(a, b, lane);
        __syncthreads();
        #pragma unroll
        for (int i = 0; i < 8; i++) {
            tt[sub * 8 + i][grp]      = a[i];
            tt[sub * 8 + i][grp + 32] = b[i];
        }
        __syncthreads();
    }

    uint32_t* dst = &g_f2p[(size_t)blockIdx.x * HW];
    #pragma unroll
    for (int i = 0; i < 16; i++) {
        int idx = tid + i * 256;
        __half2 h = __floats2half2_rn(t0[idx >> 6][idx & 63], t1[idx >> 6][idx & 63]);
        dst[idx] = *reinterpret_cast<uint32_t*>(&h);
    }
}

// ---------------------------------------------------------------------------
// Kernel 2: fused dual-pod fp16 GEMM + v-scale + softthr + pod-sum.
// BM=128 x BN=64, warp 32x32, K=256 in EIGHT 32-wide chunks (2 mma k-steps
// per chunk), 3-stage cp.async, XOR-swizzled B, LDS.128 A frags.
// Output: half2 (c, c+8) packed -> g_f6h.
// ---------------------------------------------------------------------------
#define A_STG 4096                        // floats/stage: 1024 uint4 = 16KB
#define B_STG 1024                        // floats/stage: 16 cpair * 64 half2 = 4KB
#define STG   (A_STG + B_STG)             // 5120 floats = 20KB
#define NSTAGE 3
#define GEMM_SMEM_BYTES (NSTAGE * STG * 4)   // 61440

__device__ __forceinline__ void cp_async16(void* smem, const void* gmem) {
    uint32_t s = (uint32_t)__cvta_generic_to_shared(smem);
    asm volatile("cp.async.ca.shared.global [%0], [%1], 16;\n" :: "r"(s), "l"(gmem));
}

__device__ __forceinline__ void mma_f16(float& d0, float& d1, float& d2, float& d3,
                                        uint32_t a0, uint32_t a1, uint32_t a2, uint32_t a3,
                                        uint32_t b0, uint32_t b1) {
    asm volatile(
        "mma.sync.aligned.m16n8k16.row.col.f32.f16.f16.f32 "
        "{%0,%1,%2,%3}, {%4,%5,%6,%7}, {%8,%9}, {%0,%1,%2,%3};\n"
        : "+f"(d0), "+f"(d1), "+f"(d2), "+f"(d3)
        : "r"(a0), "r"(a1), "r"(a2), "r"(a3), "r"(b0), "r"(b1));
}

__global__ __launch_bounds__(256) void k_gemm_fused(const float* __restrict__ v,
                                                    const float* __restrict__ T) {
    extern __shared__ float smem[];

    const int tid  = threadIdx.x;
    const int warp = tid >> 5;
    const int lane = tid & 31;
    const int g = lane >> 2;
    const int t = lane & 3;
    const int warp_m = warp & 3;
    const int warp_n = warp >> 2;

    const int n0 = blockIdx.x * 64;
    const int m0 = blockIdx.y * 128;
    const int m16base = blockIdx.y * 8;
    const int b  = blockIdx.z;

    const uint32_t* f2b = g_f2p + (size_t)b * (CH / 2) * HW;

    // one chunk = K 32: A layout [kq(2)][p(2)][mtile(8)][lane(32)] uint4
    auto prefetch = [&](int kc, int st) {
        #pragma unroll
        for (int i = 0; i < 4; i++) {
            int u  = i * 256 + tid;              // 0..1023
            int kq = u >> 9;
            int p  = (u >> 8) & 1;
            int mm = (u >> 5) & 7;
            int ln = u & 31;
            const uint4* src = &g_WtFh[((p * 16 + kc * 2 + kq) * 16 + m16base + mm) * 32 + ln];
            cp_async16(&smem[st * STG + u * 4], src);
        }
        // B: 16 cpair rows x 64 half2 cols; swizzle chunk ^= (cpair&3)<<3
        {
            int kk = tid >> 4;                   // cpair 0..15
            int c4 = (tid & 15) * 4;
            int phys = c4 ^ ((kk & 3) << 3);
            cp_async16(&smem[st * STG + A_STG + kk * 64 + phys],
                       &f2b[(size_t)(kc * 16 + kk) * HW + n0 + c4]);
        }
        asm volatile("cp.async.commit_group;\n");
    };

    float acc[2][2][4][4];
    #pragma unroll
    for (int p = 0; p < 2; p++)
        #pragma unroll
        for (int mt = 0; mt < 2; mt++)
            #pragma unroll
            for (int nt = 0; nt < 4; nt++)
                #pragma unroll
                for (int r = 0; r < 4; r++) acc[p][mt][nt][r] = 0.0f;

    prefetch(0, 0);
    prefetch(1, 1);

    for (int kc = 0; kc < 8; kc++) {
        const int st = kc % NSTAGE;
        __syncthreads();
        if (kc + 2 < 8) prefetch(kc + 2, (kc + 2) % NSTAGE);
        else asm volatile("cp.async.commit_group;\n");
        asm volatile("cp.async.wait_group 2;\n");
        __syncthreads();

        const uint32_t* sB = reinterpret_cast<const uint32_t*>(&smem[st * STG + A_STG]);
        const uint4*    sA = reinterpret_cast<const uint4*>(&smem[st * STG]);

        #pragma unroll
        for (int kq = 0; kq < 2; kq++) {
            // B frags: rows kq*8 + t and + t+4; (r&3)==t either way
            uint32_t bf[4][2];
            #pragma unroll
            for (int nt = 0; nt < 4; nt++) {
                int n = warp_n * 32 + nt * 8 + g;
                int col = n ^ (t << 3);
                bf[nt][0] = sB[(kq * 8 + t) * 64 + col];
                bf[nt][1] = sB[(kq * 8 + t + 4) * 64 + col];
            }
            #pragma unroll
            for (int p = 0; p < 2; p++) {
                #pragma unroll
                for (int mt = 0; mt < 2; mt++) {
                    int u = ((kq * 2 + p) * 8 + warp_m * 2 + mt) * 32 + lane;
                    uint4 af = sA[u];
                    #pragma unroll
                    for (int nt = 0; nt < 4; nt++)
                        mma_f16(acc[p][mt][nt][0], acc[p][mt][nt][1],
                                acc[p][mt][nt][2], acc[p][mt][nt][3],
                                af.x, af.y, af.z, af.w, bf[nt][0], bf[nt][1]);
                }
            }
        }
    }

    // Epilogue: v-scale, softthr, pod-sum; pack rows (o, o+8) into half2
    uint32_t* f6b = g_f6h + (size_t)b * (CH / 2) * HW;
    #pragma unroll
    for (int nt = 0; nt < 4; nt++) {
        int hw = n0 + warp_n * 32 + nt * 8 + 2 * t;
        float v0[2], v1[2], t0[2], t1[2];
        #pragma unroll
        for (int p = 0; p < 2; p++) {
            v0[p] = v[p * HW + hw];
            v1[p] = v[p * HW + hw + 1];
            t0[p] = T[p * HW + hw];
            t1[p] = T[p * HW + hw + 1];
        }
        #pragma unroll
        for (int mt = 0; mt < 2; mt++) {
            int base16 = m0 + warp_m * 32 + mt * 16;     // multiple of 16
            int pc = (base16 >> 4) * 8 + g;              // pair id: rows (base16+g, +8)
            float s0 = 0.f, s1 = 0.f, s2 = 0.f, s3 = 0.f;
            #pragma unroll
            for (int p = 0; p < 2; p++) {
                s0 += softthr(v0[p] * acc[p][mt][nt][0], t0[p]);
                s1 += softthr(v1[p] * acc[p][mt][nt][1], t1[p]);
                s2 += softthr(v0[p] * acc[p][mt][nt][2], t0[p]);
                s3 += softthr(v1[p] * acc[p][mt][nt][3], t1[p]);
            }
            __half2 h0 = __floats2half2_rn(s0, s2);      // (row, row+8) @ hw
            __half2 h1 = __floats2half2_rn(s1, s3);      // (row, row+8) @ hw+1
            uint2 pk;
            pk.x = *reinterpret_cast<uint32_t*>(&h0);
            pk.y = *reinterpret_cast<uint32_t*>(&h1);
            *reinterpret_cast<uint2*>(&f6b[(size_t)pc * HW + hw]) = pk;
        }
    }
}

// ---------------------------------------------------------------------------
// Kernel 3: inverse 2D FWHT (*1/4096) + residual on a CHANNEL PAIR (c, c+8).
// ---------------------------------------------------------------------------
__global__ __launch_bounds__(256) void k_fwht_inv(const float* __restrict__ x,
                                                  float* __restrict__ out) {
    __shared__ float t0[64][65];
    __shared__ float t1[64][65];
    const int pcg = blockIdx.x;               // [b(32)][pc(128)]
    const int b   = pcg >> 7;
    const int pc  = pcg & 127;
    const int c0  = (pc >> 3) * 16 + (pc & 7);
    const int tid = threadIdx.x, lane = tid & 31;
    const int sub = tid & 7;
    const int grp = tid >> 3;
    float a[8], bb[8];

    // unpack f6h pair into two tiles
    const uint32_t* src = &g_f6h[(size_t)pcg * HW];
    #pragma unroll
    for (int i = 0; i < 16; i++) {
        int idx = tid + i * 256;
        uint32_t u = src[idx];
        __half2 h = *reinterpret_cast<__half2*>(&u);
        float2 f = __half22float2(h);
        t0[idx >> 6][idx & 63] = f.x;
        t1[idx >> 6][idx & 63] = f.y;
    }
    __syncthreads();

    #pragma unroll
    for (int img = 0; img < 2; img++) {
        float (*tt)[65] = img ? t1 : t0;
        // row pass (thread-private read/write of same addresses)
        #pragma unroll
        for (int i = 0; i < 8; i++) {
            a[i]  = tt[grp][sub * 8 + i];
            bb[i] = tt[grp + 32][sub * 8 + i];
        }
        wht64_vec(a, bb, lane);
        #pragma unroll
        for (int i = 0; i < 8; i++) {
            tt[grp][sub * 8 + i]      = a[i];
            tt[grp + 32][sub * 8 + i] = bb[i];
        }
        __syncthreads();
        // column pass
        #pragma unroll
        for (int i = 0; i < 8; i++) {
            a[i]  = tt[sub * 8 + i][grp];
            bb[i] = tt[sub * 8 + i][grp + 32];
        }
        wht64_vec(a, bb, lane);
        #pragma unroll
        for (int i = 0; i < 8; i++) {
            tt[sub * 8 + i][grp]      = a[i];
            tt[sub * 8 + i][grp + 32] = bb[i];
        }
        __syncthreads();
    }

    const float inv = 1.0f / 4096.0f;
    const size_t base0 = ((size_t)b * CH + c0) * HW;
    const size_t base1 = base0 + 8 * HW;
    #pragma unroll
    for (int i = 0; i < 16; i++) {
        int idx = tid + i * 256;
        out[base0 + idx] = fmaf(t0[idx >> 6][idx & 63], inv, x[base0 + idx]);
        out[base1 + idx] = fmaf(t1[idx >> 6][idx & 63], inv, x[base1 + idx]);
    }
}

// ---------------------------------------------------------------------------
extern "C" void kernel_launch(void* const* d_in, const int* in_sizes, int n_in,
                              void* d_out, int out_size) {
    const float* x = (const float*)d_in[0];
    const float* v = (const float*)d_in[1];
    const float* W = (const float*)d_in[2];
    const float* T = (const float*)d_in[3];
    float* out = (float*)d_out;

    cudaFuncSetAttribute(k_gemm_fused,
                         cudaFuncAttributeMaxDynamicSharedMemorySize,
                         GEMM_SMEM_BYTES);

    k_pack_w<<<(2 * 16 * 16 * 32 + 255) / 256, 256>>>(W);
    k_fwht_fwd<<<NIMG / 2, 256>>>(x);
    dim3 grid(HW / 64, CH / 128, BATCH);   // (64, 2, 32)
    k_gemm_fused<<<grid, 256, GEMM_SMEM_BYTES>>>(v, T);
    k_fwht_inv<<<BATCH * (CH / 2), 256>>>(x, out);
}

// round 16
// speedup vs baseline: 1.4753x; 1.0172x over previous
#include <cuda_runtime.h>
#include <cuda_fp16.h>
#include <cstdint>

// ---------------------------------------------------------------------------
// x: (32, 256, 64, 64) f32   v: (2, 64, 64)   W: (2, 256, 256)   T: (2, 64, 64)
// out = invWHT( sum_p soft( v_p * (W_p @ WHT(x)), T_p ) ) / 4096 + x
// GEMM fp16 (m16n8k16, fp32 acc); f2 and f6 stored as packed half2.
// Transforms: 512-thread blocks, one 256-thread half per image of the pair.
// ---------------------------------------------------------------------------

#define BATCH 32
#define CH    256
#define HW    4096
#define NIMG  (BATCH * CH)

// f2 as half2, channel-pair interleaved: [b][c/2][hw] -> half2(c_even, c_odd)
__device__ uint32_t g_f2p[(size_t)BATCH * (CH / 2) * HW];     // 64 MB
// f6 as half2, pair (c, c+8) within each 16-row tile: [b][pc][hw],
//   pc = (c>>4)*8 + (c&7), pair = (c, c+8)
__device__ uint32_t g_f6h[(size_t)BATCH * (CH / 2) * HW];     // 64 MB
// W fp16 in m16n8k16 A-fragment order: [pod(2)][kc16(16)][mtile(16)][lane(32)] x uint4
__device__ uint4    g_WtFh[2 * 16 * 16 * 32];

__device__ __forceinline__ float softthr(float s, float t) {
    float m = fmaxf(fabsf(s) - t, 0.0f);
    return copysignf(m, s);
}

// ---------------------------------------------------------------------------
// 64-pt WHT, 8 consecutive elements/thread; stages 1,2,4 register-local,
// stages 8,16,32 via shfl.xor masks 1,2,4.
// ---------------------------------------------------------------------------
__device__ __forceinline__ void wht8_local(float (&a)[8]) {
    #pragma unroll
    for (int j = 0; j < 8; j += 2) { float s = a[j] + a[j+1], d = a[j] - a[j+1]; a[j] = s; a[j+1] = d; }
    #pragma unroll
    for (int j0 = 0; j0 < 8; j0 += 4)
        #pragma unroll
        for (int j = j0; j < j0 + 2; j++) { float s = a[j] + a[j+2], d = a[j] - a[j+2]; a[j] = s; a[j+2] = d; }
    #pragma unroll
    for (int j = 0; j < 4; j++) { float s = a[j] + a[j+4], d = a[j] - a[j+4]; a[j] = s; a[j+4] = d; }
}

__device__ __forceinline__ void wht64_vec(float (&a)[8], float (&b)[8], int lane) {
    wht8_local(a);
    wht8_local(b);
    #pragma unroll
    for (int mask = 1; mask <= 4; mask <<= 1) {
        bool hi = (lane & mask) != 0;
        #pragma unroll
        for (int i = 0; i < 8; i++) {
            float pa = __shfl_xor_sync(0xffffffffu, a[i], mask);
            float pb = __shfl_xor_sync(0xffffffffu, b[i], mask);
            a[i] = hi ? pa - a[i] : a[i] + pa;
            b[i] = hi ? pb - b[i] : b[i] + pb;
        }
    }
}

// ---------------------------------------------------------------------------
// Kernel 0: W -> fp16 m16n8k16 A-fragment order.
// ---------------------------------------------------------------------------
__global__ void k_pack_w(const float* __restrict__ W) {
    int idx = blockIdx.x * blockDim.x + threadIdx.x;   // [p][kc][mtile][lane]
    if (idx >= 2 * 16 * 16 * 32) return;
    int lane = idx & 31;
    int mt   = (idx >> 5) & 15;
    int kc   = (idx >> 9) & 15;
    int p    = idx >> 13;
    int g = lane >> 2, t = lane & 3;
    const float* Wp = W + p * 65536;
    int m0 = mt * 16 + g, m1 = m0 + 8;
    int k0 = kc * 16 + 2 * t;
    __half2 r0 = __floats2half2_rn(Wp[m0 * 256 + k0],     Wp[m0 * 256 + k0 + 1]);
    __half2 r1 = __floats2half2_rn(Wp[m1 * 256 + k0],     Wp[m1 * 256 + k0 + 1]);
    __half2 r2 = __floats2half2_rn(Wp[m0 * 256 + k0 + 8], Wp[m0 * 256 + k0 + 9]);
    __half2 r3 = __floats2half2_rn(Wp[m1 * 256 + k0 + 8], Wp[m1 * 256 + k0 + 9]);
    uint4 u;
    u.x = *reinterpret_cast<uint32_t*>(&r0);
    u.y = *reinterpret_cast<uint32_t*>(&r1);
    u.z = *reinterpret_cast<uint32_t*>(&r2);
    u.w = *reinterpret_cast<uint32_t*>(&r3);
    g_WtFh[idx] = u;
}

// ---------------------------------------------------------------------------
// Kernel 1: forward 2D FWHT on a CHANNEL PAIR -> g_f2p half2-interleaved.
// 512 threads: half 0 transforms channel 2j, half 1 transforms channel 2j+1.
// ---------------------------------------------------------------------------
__global__ __launch_bounds__(512) void k_fwht_fwd(const float* __restrict__ x) {
    __shared__ float t0[64][65];
    __shared__ float t1[64][65];
    const size_t base0 = (size_t)blockIdx.x * 2 * HW;
    const int tid  = threadIdx.x;
    const int tid2 = tid & 255;
    const int img  = tid >> 8;
    const int lane = tid & 31;
    const int sub  = tid2 & 7;
    const int grp  = tid2 >> 3;
    float a[8], b[8];

    const float* xi = &x[base0 + (size_t)img * HW];
    float (*tt)[65] = img ? t1 : t0;

    {
        const float* r0 = &xi[grp * 64 + sub * 8];
        const float* r1 = &xi[(grp + 32) * 64 + sub * 8];
        *reinterpret_cast<float4*>(&a[0]) = *reinterpret_cast<const float4*>(r0);
        *reinterpret_cast<float4*>(&a[4]) = *reinterpret_cast<const float4*>(r0 + 4);
        *reinterpret_cast<float4*>(&b[0]) = *reinterpret_cast<const float4*>(r1);
        *reinterpret_cast<float4*>(&b[4]) = *reinterpret_cast<const float4*>(r1 + 4);
    }
    wht64_vec(a, b, lane);
    #pragma unroll
    for (int i = 0; i < 8; i++) {
        tt[grp][sub * 8 + i]      = a[i];
        tt[grp + 32][sub * 8 + i] = b[i];
    }
    __syncthreads();
    #pragma unroll
    for (int i = 0; i < 8; i++) {
        a[i] = tt[sub * 8 + i][grp];
        b[i] = tt[sub * 8 + i][grp + 32];
    }
    wht64_vec(a, b, lane);
    __syncthreads();
    #pragma unroll
    for (int i = 0; i < 8; i++) {
        tt[sub * 8 + i][grp]      = a[i];
        tt[sub * 8 + i][grp + 32] = b[i];
    }
    __syncthreads();

    // interleaved half2 write: all 512 threads, 8 elements each
    uint32_t* dst = &g_f2p[(size_t)blockIdx.x * HW];
    #pragma unroll
    for (int i = 0; i < 8; i++) {
        int idx = tid + i * 512;
        __half2 h = __floats2half2_rn(t0[idx >> 6][idx & 63], t1[idx >> 6][idx & 63]);
        dst[idx] = *reinterpret_cast<uint32_t*>(&h);
    }
}

// ---------------------------------------------------------------------------
// Kernel 2: fused dual-pod fp16 GEMM + v-scale + softthr + pod-sum.
// BM=128 x BN=64, warp 32x32, K=256 in 8 chunks of 32, 3-stage cp.async,
// XOR-swizzled B, LDS.128 A frags. Output: half2 (c, c+8) -> g_f6h.
// ---------------------------------------------------------------------------
#define A_STG 4096                        // floats/stage: 1024 uint4 = 16KB
#define B_STG 1024                        // floats/stage: 16 cpair * 64 half2 = 4KB
#define STG   (A_STG + B_STG)             // 5120 floats = 20KB
#define NSTAGE 3
#define GEMM_SMEM_BYTES (NSTAGE * STG * 4)   // 61440

__device__ __forceinline__ void cp_async16(void* smem, const void* gmem) {
    uint32_t s = (uint32_t)__cvta_generic_to_shared(smem);
    asm volatile("cp.async.ca.shared.global [%0], [%1], 16;\n" :: "r"(s), "l"(gmem));
}

__device__ __forceinline__ void mma_f16(float& d0, float& d1, float& d2, float& d3,
                                        uint32_t a0, uint32_t a1, uint32_t a2, uint32_t a3,
                                        uint32_t b0, uint32_t b1) {
    asm volatile(
        "mma.sync.aligned.m16n8k16.row.col.f32.f16.f16.f32 "
        "{%0,%1,%2,%3}, {%4,%5,%6,%7}, {%8,%9}, {%0,%1,%2,%3};\n"
        : "+f"(d0), "+f"(d1), "+f"(d2), "+f"(d3)
        : "r"(a0), "r"(a1), "r"(a2), "r"(a3), "r"(b0), "r"(b1));
}

__global__ __launch_bounds__(256) void k_gemm_fused(const float* __restrict__ v,
                                                    const float* __restrict__ T) {
    extern __shared__ float smem[];

    const int tid  = threadIdx.x;
    const int warp = tid >> 5;
    const int lane = tid & 31;
    const int g = lane >> 2;
    const int t = lane & 3;
    const int warp_m = warp & 3;
    const int warp_n = warp >> 2;

    const int n0 = blockIdx.x * 64;
    const int m0 = blockIdx.y * 128;
    const int m16base = blockIdx.y * 8;
    const int b  = blockIdx.z;

    const uint32_t* f2b = g_f2p + (size_t)b * (CH / 2) * HW;

    auto prefetch = [&](int kc, int st) {
        #pragma unroll
        for (int i = 0; i < 4; i++) {
            int u  = i * 256 + tid;              // 0..1023
            int kq = u >> 9;
            int p  = (u >> 8) & 1;
            int mm = (u >> 5) & 7;
            int ln = u & 31;
            const uint4* src = &g_WtFh[((p * 16 + kc * 2 + kq) * 16 + m16base + mm) * 32 + ln];
            cp_async16(&smem[st * STG + u * 4], src);
        }
        {
            int kk = tid >> 4;                   // cpair 0..15
            int c4 = (tid & 15) * 4;
            int phys = c4 ^ ((kk & 3) << 3);
            cp_async16(&smem[st * STG + A_STG + kk * 64 + phys],
                       &f2b[(size_t)(kc * 16 + kk) * HW + n0 + c4]);
        }
        asm volatile("cp.async.commit_group;\n");
    };

    float acc[2][2][4][4];
    #pragma unroll
    for (int p = 0; p < 2; p++)
        #pragma unroll
        for (int mt = 0; mt < 2; mt++)
            #pragma unroll
            for (int nt = 0; nt < 4; nt++)
                #pragma unroll
                for (int r = 0; r < 4; r++) acc[p][mt][nt][r] = 0.0f;

    prefetch(0, 0);
    prefetch(1, 1);

    for (int kc = 0; kc < 8; kc++) {
        const int st = kc % NSTAGE;
        __syncthreads();
        if (kc + 2 < 8) prefetch(kc + 2, (kc + 2) % NSTAGE);
        else asm volatile("cp.async.commit_group;\n");
        asm volatile("cp.async.wait_group 2;\n");
        __syncthreads();

        const uint32_t* sB = reinterpret_cast<const uint32_t*>(&smem[st * STG + A_STG]);
        const uint4*    sA = reinterpret_cast<const uint4*>(&smem[st * STG]);

        #pragma unroll
        for (int kq = 0; kq < 2; kq++) {
            uint32_t bf[4][2];
            #pragma unroll
            for (int nt = 0; nt < 4; nt++) {
                int n = warp_n * 32 + nt * 8 + g;
                int col = n ^ (t << 3);
                bf[nt][0] = sB[(kq * 8 + t) * 64 + col];
                bf[nt][1] = sB[(kq * 8 + t + 4) * 64 + col];
            }
            #pragma unroll
            for (int p = 0; p < 2; p++) {
                #pragma unroll
                for (int mt = 0; mt < 2; mt++) {
                    int u = ((kq * 2 + p) * 8 + warp_m * 2 + mt) * 32 + lane;
                    uint4 af = sA[u];
                    #pragma unroll
                    for (int nt = 0; nt < 4; nt++)
                        mma_f16(acc[p][mt][nt][0], acc[p][mt][nt][1],
                                acc[p][mt][nt][2], acc[p][mt][nt][3],
                                af.x, af.y, af.z, af.w, bf[nt][0], bf[nt][1]);
                }
            }
        }
    }

    // Epilogue: v-scale, softthr, pod-sum; pack rows (o, o+8) into half2
    uint32_t* f6b = g_f6h + (size_t)b * (CH / 2) * HW;
    #pragma unroll
    for (int nt = 0; nt < 4; nt++) {
        int hw = n0 + warp_n * 32 + nt * 8 + 2 * t;
        float v0[2], v1[2], t0[2], t1[2];
        #pragma unroll
        for (int p = 0; p < 2; p++) {
            v0[p] = v[p * HW + hw];
            v1[p] = v[p * HW + hw + 1];
            t0[p] = T[p * HW + hw];
            t1[p] = T[p * HW + hw + 1];
        }
        #pragma unroll
        for (int mt = 0; mt < 2; mt++) {
            int base16 = m0 + warp_m * 32 + mt * 16;
            int pc = (base16 >> 4) * 8 + g;
            float s0 = 0.f, s1 = 0.f, s2 = 0.f, s3 = 0.f;
            #pragma unroll
            for (int p = 0; p < 2; p++) {
                s0 += softthr(v0[p] * acc[p][mt][nt][0], t0[p]);
                s1 += softthr(v1[p] * acc[p][mt][nt][1], t1[p]);
                s2 += softthr(v0[p] * acc[p][mt][nt][2], t0[p]);
                s3 += softthr(v1[p] * acc[p][mt][nt][3], t1[p]);
            }
            __half2 h0 = __floats2half2_rn(s0, s2);
            __half2 h1 = __floats2half2_rn(s1, s3);
            uint2 pk;
            pk.x = *reinterpret_cast<uint32_t*>(&h0);
            pk.y = *reinterpret_cast<uint32_t*>(&h1);
            *reinterpret_cast<uint2*>(&f6b[(size_t)pc * HW + hw]) = pk;
        }
    }
}

// ---------------------------------------------------------------------------
// Kernel 3: inverse 2D FWHT (*1/4096) + residual on a CHANNEL PAIR (c, c+8).
// 512 threads: half 0 transforms tile0 (channel c), half 1 tile1 (c+8).
// ---------------------------------------------------------------------------
__global__ __launch_bounds__(512) void k_fwht_inv(const float* __restrict__ x,
                                                  float* __restrict__ out) {
    __shared__ float t0[64][65];
    __shared__ float t1[64][65];
    const int pcg = blockIdx.x;               // [b(32)][pc(128)]
    const int b   = pcg >> 7;
    const int pc  = pcg & 127;
    const int c0  = (pc >> 3) * 16 + (pc & 7);
    const int tid  = threadIdx.x;
    const int tid2 = tid & 255;
    const int img  = tid >> 8;
    const int lane = tid & 31;
    const int sub  = tid2 & 7;
    const int grp  = tid2 >> 3;
    float a[8], bb[8];

    // unpack f6h pair into two tiles: all 512 threads, 8 half2 each
    const uint32_t* src = &g_f6h[(size_t)pcg * HW];
    #pragma unroll
    for (int i = 0; i < 8; i++) {
        int idx = tid + i * 512;
        uint32_t u = src[idx];
        __half2 h = *reinterpret_cast<__half2*>(&u);
        float2 f = __half22float2(h);
        t0[idx >> 6][idx & 63] = f.x;
        t1[idx >> 6][idx & 63] = f.y;
    }
    __syncthreads();

    float (*tt)[65] = img ? t1 : t0;

    // row pass
    #pragma unroll
    for (int i = 0; i < 8; i++) {
        a[i]  = tt[grp][sub * 8 + i];
        bb[i] = tt[grp + 32][sub * 8 + i];
    }
    wht64_vec(a, bb, lane);
    #pragma unroll
    for (int i = 0; i < 8; i++) {
        tt[grp][sub * 8 + i]      = a[i];
        tt[grp + 32][sub * 8 + i] = bb[i];
    }
    __syncthreads();
    // column pass
    #pragma unroll
    for (int i = 0; i < 8; i++) {
        a[i]  = tt[sub * 8 + i][grp];
        bb[i] = tt[sub * 8 + i][grp + 32];
    }
    wht64_vec(a, bb, lane);
    #pragma unroll
    for (int i = 0; i < 8; i++) {
        tt[sub * 8 + i][grp]      = a[i];
        tt[sub * 8 + i][grp + 32] = bb[i];
    }
    __syncthreads();

    const float inv = 1.0f / 4096.0f;
    const size_t base0 = ((size_t)b * CH + c0) * HW;
    const size_t base1 = base0 + 8 * HW;
    #pragma unroll
    for (int i = 0; i < 8; i++) {
        int idx = tid + i * 512;
        out[base0 + idx] = fmaf(t0[idx >> 6][idx & 63], inv, x[base0 + idx]);
        out[base1 + idx] = fmaf(t1[idx >> 6][idx & 63], inv, x[base1 + idx]);
    }
}

// ---------------------------------------------------------------------------
extern "C" void kernel_launch(void* const* d_in, const int* in_sizes, int n_in,
                              void* d_out, int out_size) {
    const float* x = (const float*)d_in[0];
    const float* v = (const float*)d_in[1];
    const float* W = (const float*)d_in[2];
    const float* T = (const float*)d_in[3];
    float* out = (float*)d_out;

    cudaFuncSetAttribute(k_gemm_fused,
                         cudaFuncAttributeMaxDynamicSharedMemorySize,
                         GEMM_SMEM_BYTES);

    k_pack_w<<<(2 * 16 * 16 * 32 + 255) / 256, 256>>>(W);
    k_fwht_fwd<<<NIMG / 2, 512>>>(x);
    dim3 grid(HW / 64, CH / 128, BATCH);   // (64, 2, 32)
    k_gemm_fused<<<grid, 256, GEMM_SMEM_BYTES>>>(v, T);
    k_fwht_inv<<<BATCH * (CH / 2), 512>>>(x, out);
}